// round 13
// baseline (speedup 1.0000x reference)
#include <cuda_runtime.h>

#define NCLS 80
#define DIM 256
#define NMAX 65536
#define CAP 1024           // per-class bucket capacity (mean 819, +7 sigma)
#define EPSF 1e-7f
#define LOSSW 0.01f
#define JPW 8              // entries per work item
#define WPC (CAP / JPW)    // work items per class = 128
#define NITEM (NCLS * WPC) // 10240 work items
#define NBLK 512           // persistent grid (4/SM x 148 = 592 capacity)
#define NWARP (NBLK * 8)   // 4096 warps
#define BUCKET_BLOCKS 128  // blocks participating in phase 1

// ---------------- device scratch (no allocations allowed) ----------------
// Zero-initialized at load. INVARIANT: phase 3 restores g_seg/g_counts/g_t1/
// g_t2/g_done to zero, and barrier counters return to zero (generations are
// monotonic but never affect output), so graph replays are deterministic.
__device__ float g_seg[NCLS * DIM];      // class segment sums
__device__ int   g_counts[NCLS];         // cursor during bucket, count after
__device__ int   g_bucket[NCLS * CAP];   // per-class row indices
__device__ float g_t1[64];               // partial accumulators for term1
__device__ float g_t2;                   // accumulated term2
__device__ int   g_done;                 // phase-3 completion counter
__device__ int   g_bar_count[2];         // grid barrier arrival counters
__device__ int   g_bar_gen[2];           // grid barrier generations (monotonic)

__device__ __forceinline__ int clampc(int c) {
    return (c < 0) ? 0 : (c >= NCLS ? NCLS - 1 : c);
}

// x*ln(x) via MUFU.LG2; exact 0 at x==0.
__device__ __forceinline__ float xlnxf(float x) {
    float l = __logf(x);
    return (x > 0.0f) ? x * l : 0.0f;
}

__device__ __forceinline__ float warp_sum(float v) {
#pragma unroll
    for (int o = 16; o; o >>= 1)
        v += __shfl_xor_sync(0xffffffffu, v, o);
    return v;
}

// Grid-wide barrier, generation-counting (no in-launch reset race).
// Safe because all NBLK blocks are guaranteed concurrently resident
// (__launch_bounds__(256,4): 4 CTAs/SM x 148 SMs = 592 >= NBLK).
__device__ __forceinline__ void grid_barrier(int idx) {
    __syncthreads();
    __threadfence();
    if (threadIdx.x == 0) {
        volatile int* genp = &g_bar_gen[idx];
        int g = *genp;
        int old = atomicAdd(&g_bar_count[idx], 1);
        if (old == NBLK - 1) {
            g_bar_count[idx] = 0;      // safe: all blocks have arrived
            __threadfence();
            atomicAdd(&g_bar_gen[idx], 1);
        } else {
            while (*genp == g) { }
        }
    }
    __syncthreads();
    __threadfence();
}

// ---------------- single persistent kernel: bucket | main | final ----------
__global__ void __launch_bounds__(256, 4) k_fused(
        const float* __restrict__ x0, const float* __restrict__ x1,
        const float* __restrict__ x2, const int* __restrict__ labels,
        int N, float* __restrict__ out) {
    __shared__ int   h[NCLS];     // phase 1: block count, then local cursor
    __shared__ int   base[NCLS];  // phase 1: reserved global base per class
    __shared__ float red[8];
    __shared__ bool  amLast;

    int tid  = threadIdx.x;
    int bid  = blockIdx.x;
    int lane = tid & 31;
    int wid  = tid >> 5;

    // ============ Phase 1: histogram + bucket scatter (blocks 0..127) ======
    if (bid < BUCKET_BLOCKS) {
        for (int c = tid; c < NCLS; c += blockDim.x) h[c] = 0;
        __syncthreads();
        int i0 = bid * 512 + tid;
        int i1 = i0 + 256;
        int c0 = -1, c1 = -1;
        if (i0 < N) { c0 = clampc(labels[i0]); atomicAdd(&h[c0], 1); }
        if (i1 < N) { c1 = clampc(labels[i1]); atomicAdd(&h[c1], 1); }
        __syncthreads();
        for (int cc = tid; cc < NCLS; cc += blockDim.x) {
            int cnt = h[cc];
            base[cc] = cnt ? atomicAdd(&g_counts[cc], cnt) : 0;
            h[cc] = 0;
        }
        __syncthreads();
        if (i0 < N) {
            int p = base[c0] + atomicAdd(&h[c0], 1);
            if (p < CAP) g_bucket[c0 * CAP + p] = i0;
        }
        if (i1 < N) {
            int p = base[c1] + atomicAdd(&h[c1], 1);
            if (p < CAP) g_bucket[c1 * CAP + p] = i1;
        }
    }
    grid_barrier(0);

    // ============ Phase 2: main streaming pass (all warps) =================
    {
        int gwarp = bid * 8 + wid;
        float t1l = 0.0f;

        for (int item = gwarp; item < NITEM; item += NWARP) {
            int c     = item / WPC;
            int chunk = item % WPC;
            int count = g_counts[c];
            int pos0  = chunk * JPW;
            if (pos0 >= count) continue;
            int pend = min(pos0 + JPW, min(count, CAP));
            float ic3 = 1.0f / (3.0f * (float)count);

            float acc[8];
#pragma unroll
            for (int k = 0; k < 8; k++) acc[k] = 0.0f;

            for (int pos = pos0; pos < pend; pos++) {
                int j = g_bucket[c * CAP + pos];

                size_t off = (size_t)j * DIM;
                const float4* r0 = (const float4*)(x0 + off);
                const float4* r1 = (const float4*)(x1 + off);
                const float4* r2 = (const float4*)(x2 + off);
                float4 A[3], B[3];
                A[0] = __ldcs(r0 + lane); B[0] = __ldcs(r0 + 32 + lane);
                A[1] = __ldcs(r1 + lane); B[1] = __ldcs(r1 + 32 + lane);
                A[2] = __ldcs(r2 + lane); B[2] = __ldcs(r2 + 32 + lane);

#pragma unroll
                for (int mm = 0; mm < 3; mm++) {
                    float4 a = A[mm];
                    float4 b = B[mm];

                    float s1l = ((a.x + a.y) + (a.z + a.w)) +
                                ((b.x + b.y) + (b.z + b.w));
                    float s2  = fmaf(a.x, a.x, fmaf(a.y, a.y,
                                fmaf(a.z, a.z, a.w * a.w)));
                    s2 = fmaf(b.x, b.x, fmaf(b.y, b.y,
                         fmaf(b.z, b.z, fmaf(b.w, b.w, s2))));
                    float sxl = ((xlnxf(a.x) + xlnxf(a.y)) +
                                 (xlnxf(a.z) + xlnxf(a.w)))
                              + ((xlnxf(b.x) + xlnxf(b.y)) +
                                 (xlnxf(b.z) + xlnxf(b.w)));

                    s2 = warp_sum(s2);               // norm broadcast
                    s2 = fmaxf(s2, 1e-24f);          // denom >= 1e-12
                    float w   = rsqrtf(s2);          // 1/denom
                    float lnd = 0.5f * __logf(s2);   // ln(denom)
                    float wic = w * ic3;
                    t1l = fmaf(wic, fmaf(-lnd, s1l, sxl), t1l);

                    acc[0] = fmaf(a.x, w, acc[0]);
                    acc[1] = fmaf(a.y, w, acc[1]);
                    acc[2] = fmaf(a.z, w, acc[2]);
                    acc[3] = fmaf(a.w, w, acc[3]);
                    acc[4] = fmaf(b.x, w, acc[4]);
                    acc[5] = fmaf(b.y, w, acc[5]);
                    acc[6] = fmaf(b.z, w, acc[6]);
                    acc[7] = fmaf(b.w, w, acc[7]);
                }
            }

#pragma unroll
            for (int k = 0; k < 4; k++) {
                atomicAdd(&g_seg[c * DIM + lane * 4 + k],       acc[k]);
                atomicAdd(&g_seg[c * DIM + 128 + lane * 4 + k], acc[4 + k]);
            }
        }

        t1l = warp_sum(t1l);
        if (lane == 0) atomicAdd(&g_t1[(bid * 8 + wid) & 63], t1l);
    }
    grid_barrier(1);

    // ============ Phase 3: finalize (blocks 0..79, one class each) =========
    if (bid < NCLS) {
        int c = bid;
        int cnt = g_counts[c];
        float t2 = 0.0f;
        if (cnt > 0) {
            float icnt3 = 1.0f / (3.0f * (float)cnt);
            float s     = g_seg[c * DIM + tid];
            float mix   = s * icnt3;
            t2 = s * __logf(fmaxf(mix, EPSF)) * icnt3;
        }
        // restore scratch for next replay
        g_seg[c * DIM + tid] = 0.0f;
        if (tid == 0) g_counts[c] = 0;

        t2 = warp_sum(t2);
        if (lane == 0) red[wid] = t2;
        __syncthreads();
        if (wid == 0) {
            float v = (lane < 8) ? red[lane] : 0.0f;
#pragma unroll
            for (int o = 4; o; o >>= 1)
                v += __shfl_xor_sync(0xffffffffu, v, o);
            if (lane == 0) {
                atomicAdd(&g_t2, v);
                __threadfence();
                amLast = (atomicAdd(&g_done, 1) == NCLS - 1);
            }
        }
        __syncthreads();

        if (amLast) {
            float t1 = (tid < 64) ? g_t1[tid] : 0.0f;
            if (tid < 64) g_t1[tid] = 0.0f;
            t1 = warp_sum(t1);
            if (lane == 0) red[wid] = t1;   // warps 0,1 carry partials
            __syncthreads();
            if (tid == 0) {
                float tt = red[0] + red[1];
                float loss = (tt - g_t2) / (float)DIM;
                out[0] = LOSSW * loss;
                g_t2   = 0.0f;
                g_done = 0;
            }
        }
    }
}

// ---------------- launch ----------------
extern "C" void kernel_launch(void* const* d_in, const int* in_sizes, int n_in,
                              void* d_out, int out_size) {
    const float* x0  = (const float*)d_in[0];
    const float* x1  = (const float*)d_in[1];
    const float* x2  = (const float*)d_in[2];
    const int*   lab = (const int*)d_in[3];
    int N = in_sizes[3];
    if (N > NMAX) N = NMAX;

    k_fused<<<NBLK, 256>>>(x0, x1, x2, lab, N, (float*)d_out);
}

// round 14
// speedup vs baseline: 1.3365x; 1.3365x over previous
#include <cuda_runtime.h>

#define NCLS 80
#define DIM 256
#define NMAX 65536
#define CAP 1024          // per-class bucket capacity (mean 819, +7 sigma)
#define EPSF 1e-7f
#define LOSSW 0.01f
#define LN2F 0.69314718056f
#define JPW 8             // entries per warp
#define WPC (CAP / JPW)   // warps per class = 128

// ---------------- device scratch (no allocations allowed) ----------------
// Zero-initialized at module load. INVARIANT: every kernel_launch leaves all
// scratch back at zero (each kernel restores what it consumed).
__device__ float g_seg[NCLS * DIM];      // class segment sums
__device__ int   g_counts[NCLS];         // cursor during bucket, count after
__device__ int   g_bucket[NCLS * CAP];   // per-class row indices
__device__ float g_t1[64];               // partial accumulators for term1
__device__ float g_t2;                   // accumulated term2
__device__ int   g_done;                 // k_final completion counter

__device__ __forceinline__ int clampc(int c) {
    return (c < 0) ? 0 : (c >= NCLS ? NCLS - 1 : c);
}

__device__ __forceinline__ float warp_sum(float v) {
#pragma unroll
    for (int o = 16; o; o >>= 1)
        v += __shfl_xor_sync(0xffffffffu, v, o);
    return v;
}

// ---------------- K1: fused histogram + bucket scatter (R9-proven) --------
__global__ void k_bucket(const int* __restrict__ labels, int N) {
    __shared__ int h[NCLS];     // block count, then local cursor
    __shared__ int base[NCLS];  // reserved global base per class
    int tid = threadIdx.x;
    for (int c = tid; c < NCLS; c += blockDim.x) h[c] = 0;
    __syncthreads();
    int i0 = blockIdx.x * (blockDim.x * 2) + tid;
    int i1 = i0 + blockDim.x;
    int c0 = -1, c1 = -1;
    if (i0 < N) { c0 = clampc(labels[i0]); atomicAdd(&h[c0], 1); }
    if (i1 < N) { c1 = clampc(labels[i1]); atomicAdd(&h[c1], 1); }
    __syncthreads();
    for (int cc = tid; cc < NCLS; cc += blockDim.x) {
        int cnt = h[cc];
        base[cc] = cnt ? atomicAdd(&g_counts[cc], cnt) : 0;
        h[cc] = 0;
    }
    __syncthreads();
    if (i0 < N) {
        int p = base[c0] + atomicAdd(&h[c0], 1);
        if (p < CAP) g_bucket[c0 * CAP + p] = i0;
    }
    if (i1 < N) {
        int p = base[c1] + atomicAdd(&h[c1], 1);
        if (p < CAP) g_bucket[c1 * CAP + p] = i1;
    }
}

// Per-lane row partials in log2 domain: s2 += x^2, s1 += x, sx2 += x*log2(x).
// fmaxf clamp kills the 0*log(0) case with NO predicate/select ops.
__device__ __forceinline__ void row_part(float x, float& s1, float& s2, float& sx2) {
    s2  = fmaf(x, x, s2);
    s1 += x;
    float lg = __log2f(fmaxf(x, 1e-37f));
    sx2 = fmaf(x, lg, sx2);
}

// ---------------- K2: fused single-pass main kernel ----------------
// warp = (class, chunk): branch-free hot loop; lane owns 8 columns.
// The three rows' norm butterflies are interleaved (latency overlaps 3x);
// all elementwise logs are independent MUFU work the scheduler can slot in.
__global__ void __launch_bounds__(256) k_main(
        const float* __restrict__ x0, const float* __restrict__ x1,
        const float* __restrict__ x2) {
    int gwarp = (blockIdx.x * blockDim.x + threadIdx.x) >> 5;
    int lane  = threadIdx.x & 31;
    int c     = gwarp / WPC;
    int chunk = gwarp % WPC;
    if (c >= NCLS) return;

    int count = g_counts[c];
    int pos0  = chunk * JPW;
    if (pos0 >= count) return;
    int pend = min(pos0 + JPW, min(count, CAP));
    float ic3    = 1.0f / (3.0f * (float)count);
    float ic3ln2 = ic3 * LN2F;   // folds the log2->ln conversion, once

    float acc[8];
#pragma unroll
    for (int k = 0; k < 8; k++) acc[k] = 0.0f;
    float t1l = 0.0f;

    for (int pos = pos0; pos < pend; pos++) {
        int j = g_bucket[c * CAP + pos];

        size_t off = (size_t)j * DIM;
        const float4* r0 = (const float4*)(x0 + off);
        const float4* r1 = (const float4*)(x1 + off);
        const float4* r2 = (const float4*)(x2 + off);
        float4 A[3], B[3];
        A[0] = __ldcs(r0 + lane); B[0] = __ldcs(r0 + 32 + lane);
        A[1] = __ldcs(r1 + lane); B[1] = __ldcs(r1 + 32 + lane);
        A[2] = __ldcs(r2 + lane); B[2] = __ldcs(r2 + 32 + lane);

        float s1v[3], s2v[3], sx2[3];
#pragma unroll
        for (int mm = 0; mm < 3; mm++) {
            float s1 = 0.0f, s2 = 0.0f, sx = 0.0f;
            row_part(A[mm].x, s1, s2, sx);
            row_part(A[mm].y, s1, s2, sx);
            row_part(A[mm].z, s1, s2, sx);
            row_part(A[mm].w, s1, s2, sx);
            row_part(B[mm].x, s1, s2, sx);
            row_part(B[mm].y, s1, s2, sx);
            row_part(B[mm].z, s1, s2, sx);
            row_part(B[mm].w, s1, s2, sx);
            s1v[mm] = s1; s2v[mm] = s2; sx2[mm] = sx;
        }

        // Interleaved butterflies: the three reductions' shfl latencies overlap.
#pragma unroll
        for (int o = 16; o; o >>= 1) {
            s2v[0] += __shfl_xor_sync(0xffffffffu, s2v[0], o);
            s2v[1] += __shfl_xor_sync(0xffffffffu, s2v[1], o);
            s2v[2] += __shfl_xor_sync(0xffffffffu, s2v[2], o);
        }

#pragma unroll
        for (int mm = 0; mm < 3; mm++) {
            float s2  = fmaxf(s2v[mm], 1e-24f);  // denom = sqrt(s2) >= 1e-12
            float w   = rsqrtf(s2);              // 1/denom
            float l2d = 0.5f * __log2f(s2);      // log2(denom)
            // t1 += w*ic3*ln2*(sx2_l - l2d*s1_l)   [per-lane partial]
            t1l = fmaf(w * ic3ln2, fmaf(-l2d, s1v[mm], sx2[mm]), t1l);

            acc[0] = fmaf(A[mm].x, w, acc[0]);
            acc[1] = fmaf(A[mm].y, w, acc[1]);
            acc[2] = fmaf(A[mm].z, w, acc[2]);
            acc[3] = fmaf(A[mm].w, w, acc[3]);
            acc[4] = fmaf(B[mm].x, w, acc[4]);
            acc[5] = fmaf(B[mm].y, w, acc[5]);
            acc[6] = fmaf(B[mm].z, w, acc[6]);
            acc[7] = fmaf(B[mm].w, w, acc[7]);
        }
    }

    // One flush per warp (class fixed).
#pragma unroll
    for (int k = 0; k < 4; k++) {
        atomicAdd(&g_seg[c * DIM + lane * 4 + k],       acc[k]);
        atomicAdd(&g_seg[c * DIM + 128 + lane * 4 + k], acc[4 + k]);
    }
    t1l = warp_sum(t1l);
    if (lane == 0) atomicAdd(&g_t1[gwarp & 63], t1l);
}

// ---------------- K3: finalize + combine (last-block pattern) ----------------
__global__ void k_final(float* __restrict__ out) {
    __shared__ float red[8];
    __shared__ bool  amLast;
    int c    = blockIdx.x;
    int d    = threadIdx.x;
    int lane = d & 31;
    int wid  = d >> 5;

    int cnt = g_counts[c];
    float t2 = 0.0f;
    if (cnt > 0) {
        float icnt3 = 1.0f / (3.0f * (float)cnt);
        float s     = g_seg[c * DIM + d];
        float mix   = s * icnt3;
        t2 = s * __logf(fmaxf(mix, EPSF)) * icnt3;
    }
    // restore scratch for next replay
    g_seg[c * DIM + d] = 0.0f;
    if (d == 0) g_counts[c] = 0;

    t2 = warp_sum(t2);
    if (lane == 0) red[wid] = t2;
    __syncthreads();
    if (wid == 0) {
        float v = (lane < 8) ? red[lane] : 0.0f;
#pragma unroll
        for (int o = 4; o; o >>= 1)
            v += __shfl_xor_sync(0xffffffffu, v, o);
        if (lane == 0) {
            atomicAdd(&g_t2, v);
            __threadfence();
            amLast = (atomicAdd(&g_done, 1) == NCLS - 1);
        }
    }
    __syncthreads();

    if (amLast) {
        float t1 = (d < 64) ? g_t1[d] : 0.0f;
        if (d < 64) g_t1[d] = 0.0f;
        t1 = warp_sum(t1);
        if (lane == 0) red[wid] = t1;   // warps 0,1 carry partials; rest are 0
        __syncthreads();
        if (d == 0) {
            float tt = red[0] + red[1];
            float loss = (tt - g_t2) / (float)DIM;
            out[0] = LOSSW * loss;
            g_t2   = 0.0f;
            g_done = 0;
        }
    }
}

// ---------------- launch ----------------
extern "C" void kernel_launch(void* const* d_in, const int* in_sizes, int n_in,
                              void* d_out, int out_size) {
    const float* x0  = (const float*)d_in[0];
    const float* x1  = (const float*)d_in[1];
    const float* x2  = (const float*)d_in[2];
    const int*   lab = (const int*)d_in[3];
    int N = in_sizes[3];
    if (N > NMAX) N = NMAX;

    k_bucket<<<(N + 1023) / 1024, 512>>>(lab, N);

    // 80 classes x 128 warps-per-class = 10240 warps = 1280 blocks of 256.
    k_main<<<NCLS * WPC / 8, 256>>>(x0, x1, x2);

    k_final<<<NCLS, 256>>>((float*)d_out);
}